// round 15
// baseline (speedup 1.0000x reference)
#include <cuda_runtime.h>
#include <cuda_bf16.h>
#include <cstdint>

// B=8, L=4000, D=512, WINDOW=5.
// Identity: shift/unshift cancel -> per column c, sort consecutive 5-row
// windows whose start rows are ≡ c (mod 5), circular over L.
//
// R15 = R14 (ring-buffer persistent CTAs, RING=48, decoupled early loads)
// + FRACTIONAL L2 POLICY for the output. Input: evict_last 1.0 (65.5MB
// pinned; the R12 win). Output: evict_last frac 0.8 / evict_first secondary
// -> ~52MB of output lines stay L2-resident (dirty lines are rewritten in L2
// each replay, no DRAM write-back), ~13MB streams. Total pinned ~117MB < 126MB
// L2, avoiding R13's all-pinned cyclic thrash. Steady-state DRAM traffic
// ~87MB -> ~15-20MB per replay.

#define LROWS 4000
#define DCOLS 512
#define ROWBYTES (DCOLS * 4)        // 2048
#define TROWS 10
#define RING 48
#define NTILES (LROWS / TROWS)      // 400 per batch
#define GPB 37                      // 37*8 = 296 CTAs = one wave
#define NTHREADS 512
#define SMEM_BYTES (RING * ROWBYTES + 64)

#define CE(x, y) { float _lo = fminf(x, y); float _hi = fmaxf(x, y); x = _lo; y = _hi; }

__device__ __forceinline__ void load_rows(const float* vb, int first, int n,
                                          uint32_t ring_base, uint32_t mbar,
                                          uint64_t pol_last)
{
    asm volatile("mbarrier.arrive.expect_tx.shared.b64 _, [%0], %1;"
                 :: "r"(mbar), "r"((uint32_t)(n * ROWBYTES)) : "memory");
    for (int r = first; r < first + n; r++) {
        int gs = r; if (gs < 0) gs += LROWS; else if (gs >= LROWS) gs -= LROWS;
        int rr = r % RING; if (rr < 0) rr += RING;
        asm volatile(
            "cp.async.bulk.shared::cta.global.mbarrier::complete_tx::bytes"
            ".L2::cache_hint [%0], [%1], %2, [%3], %4;"
            :: "r"(ring_base + (uint32_t)(rr * ROWBYTES)),
               "l"((const char*)(vb + (size_t)gs * DCOLS)),
               "r"((uint32_t)ROWBYTES), "r"(mbar), "l"(pol_last) : "memory");
    }
}

__device__ __forceinline__ void mbar_wait(uint32_t mbar, uint32_t phase)
{
    uint32_t done;
    asm volatile(
        "{\n\t.reg .pred p;\n\t"
        "mbarrier.try_wait.parity.acquire.cta.shared::cta.b64 p, [%1], %2;\n\t"
        "selp.b32 %0, 1, 0, p;\n\t}"
        : "=r"(done) : "r"(mbar), "r"(phase) : "memory");
    if (!done) {
        asm volatile(
            "{\n\t.reg .pred P1;\n\t"
            "WL_%=:\n\t"
            "mbarrier.try_wait.parity.acquire.cta.shared::cta.b64 P1, [%0], %1, 0x989680;\n\t"
            "@P1 bra.uni WD_%=;\n\t"
            "bra.uni WL_%=;\n\t"
            "WD_%=:\n\t}"
            :: "r"(mbar), "r"(phase) : "memory");
    }
}

__device__ __forceinline__ void sort_win(float* sm, int s, int tx)
{
    int r0 = s % RING; if (r0 < 0) r0 += RING;
    int r1 = r0 + 1; if (r1 >= RING) r1 -= RING;
    int r2 = r1 + 1; if (r2 >= RING) r2 -= RING;
    int r3 = r2 + 1; if (r3 >= RING) r3 -= RING;
    int r4 = r3 + 1; if (r4 >= RING) r4 -= RING;
    float a0 = sm[r0 * DCOLS + tx];
    float a1 = sm[r1 * DCOLS + tx];
    float a2 = sm[r2 * DCOLS + tx];
    float a3 = sm[r3 * DCOLS + tx];
    float a4 = sm[r4 * DCOLS + tx];
    CE(a0, a1); CE(a3, a4); CE(a2, a4);
    CE(a2, a3); CE(a0, a3); CE(a0, a2);
    CE(a1, a4); CE(a1, a3); CE(a1, a2);
    sm[r0 * DCOLS + tx] = a0;
    sm[r1 * DCOLS + tx] = a1;
    sm[r2 * DCOLS + tx] = a2;
    sm[r3 * DCOLS + tx] = a3;
    sm[r4 * DCOLS + tx] = a4;
}

__global__ __launch_bounds__(NTHREADS, 2)
void swd_ring_kernel(const float* __restrict__ v, float* __restrict__ out) {
    extern __shared__ float sm[];
    uint32_t smem_base;
    asm("{ .reg .u64 t; cvta.to.shared.u64 t, %1; cvt.u32.u64 %0, t; }"
        : "=r"(smem_base) : "l"(sm));
    const uint32_t mbb = smem_base + RING * ROWBYTES;

    const int tx = threadIdx.x;
    const int g  = blockIdx.x;
    const int b  = blockIdx.y;

    const int t0 = (g * NTILES) / GPB;
    const int t1 = ((g + 1) * NTILES) / GPB;
    const int n  = t1 - t0;                     // 10 or 11
    const int P0 = t0 * TROWS;

    const float* __restrict__ vb = v   + (size_t)b * LROWS * DCOLS;
    float*       __restrict__ ob = out + (size_t)b * LROWS * DCOLS;

    // Input fully pinned; output 80% pinned / 20% streaming.
    uint64_t pol_last, pol_out;
    asm volatile("createpolicy.fractional.L2::evict_last.b64 %0, 1.0;"
                 : "=l"(pol_last));
    asm volatile("createpolicy.fractional.L2::evict_last.L2::evict_first.b64 %0, 0.8;"
                 : "=l"(pol_out));

    if (tx == 0) {
        #pragma unroll
        for (int j = 0; j < 4; j++)
            asm volatile("mbarrier.init.shared.b64 [%0], 1;"
                         :: "r"(mbb + 8u * j) : "memory");
    }
    __syncthreads();

    if (tx == 0) {
        load_rows(vb, P0 - 4, 19, smem_base, mbb + 0, pol_last);
        if (n > 1) load_rows(vb, P0 + 15, 10, smem_base, mbb + 8, pol_last);
    }

    const int o = (tx + 4) % 5;

    for (int i = 0; i < n; i++) {
        const int P = P0 + i * TROWS;
        mbar_wait(mbb + 8u * (i & 3), (i >> 2) & 1);

        // Early load issue for tile i+2: its ring rows (≡ P-23..P-14 mod 48)
        // belong to stores i-3/i-2; wait_group 1 guarantees both drained
        // (at most store i-1 outstanding).
        if (tx == 0 && i + 2 < n) {
            asm volatile("cp.async.bulk.wait_group 1;" ::: "memory");
            load_rows(vb, P + 25, 10, smem_base,
                      mbb + 8u * ((i + 2) & 3), pol_last);
        }

        if (i == 0) sort_win(sm, P - 4 + o, tx);
        sort_win(sm, P + 1 + o, tx);
        sort_win(sm, P + 6 + o, tx);
        __syncthreads();

        if (tx == 0) {
            asm volatile("fence.proxy.async.shared::cta;" ::: "memory");
            int rr = P % RING;                       // 0..47
            int n1 = RING - rr; if (n1 > TROWS) n1 = TROWS;
            asm volatile(
                "cp.async.bulk.global.shared::cta.bulk_group"
                ".L2::cache_hint [%0], [%1], %2, %3;"
                :: "l"((char*)(ob + (size_t)P * DCOLS)),
                   "r"(smem_base + (uint32_t)(rr * ROWBYTES)),
                   "r"((uint32_t)(n1 * ROWBYTES)), "l"(pol_out)
                : "memory");
            if (n1 < TROWS) {                        // wrapped tail from row 0
                asm volatile(
                    "cp.async.bulk.global.shared::cta.bulk_group"
                    ".L2::cache_hint [%0], [%1], %2, %3;"
                    :: "l"((char*)(ob + (size_t)(P + n1) * DCOLS)),
                       "r"(smem_base),
                       "r"((uint32_t)((TROWS - n1) * ROWBYTES)), "l"(pol_out)
                    : "memory");
            }
            asm volatile("cp.async.bulk.commit_group;" ::: "memory");
        }
    }

    if (tx == 0) {
        asm volatile("cp.async.bulk.wait_group 0;" ::: "memory");
    }
}

extern "C" void kernel_launch(void* const* d_in, const int* in_sizes, int n_in,
                              void* d_out, int out_size) {
    const float* v = (const float*)d_in[2];   // inputs: q (unused), k (unused), v
    float* out     = (float*)d_out;

    cudaFuncSetAttribute(swd_ring_kernel,
                         cudaFuncAttributeMaxDynamicSharedMemorySize, SMEM_BYTES);

    dim3 grid(GPB, 8);                        // 296 CTAs = one wave
    swd_ring_kernel<<<grid, NTHREADS, SMEM_BYTES>>>(v, out);
}

// round 16
// speedup vs baseline: 1.3535x; 1.3535x over previous
#include <cuda_runtime.h>
#include <cuda_bf16.h>
#include <cstdint>

// B=8, L=4000, D=512, WINDOW=5.
// Identity: shift/unshift cancel -> per column c, sort consecutive 5-row
// windows whose start rows are ≡ c (mod 5), circular over L.
//
// R16 = R14 (ring-buffer persistent CTAs, decoupled early loads, proven L2
// policy: input evict_last / output evict_first — R13+R15 showed any
// evict_last on the store path regresses) with RING=36 (73.8KB smem) to fit
// 3 CTAs/SM: 440 CTAs ≈ one wave at occ ~67%, 50% more concurrent bulk-load
// streams per SM. Pipeline is depth-1 (load i+1 issued at top of iter i,
// gated by wait_group 1 ≡ store i-2 drained; all overlaps re-derived for
// RING=36).

#define LROWS 4000
#define DCOLS 512
#define ROWBYTES (DCOLS * 4)        // 2048
#define TROWS 10
#define RING 36
#define NTILES (LROWS / TROWS)      // 400 per batch
#define GPB 55                      // 55*8 = 440 CTAs ≈ one wave @3/SM
#define NTHREADS 512
#define SMEM_BYTES (RING * ROWBYTES + 64)   // 73792

#define CE(x, y) { float _lo = fminf(x, y); float _hi = fmaxf(x, y); x = _lo; y = _hi; }

__device__ __forceinline__ void load_rows(const float* vb, int first, int n,
                                          uint32_t ring_base, uint32_t mbar,
                                          uint64_t pol_last)
{
    asm volatile("mbarrier.arrive.expect_tx.shared.b64 _, [%0], %1;"
                 :: "r"(mbar), "r"((uint32_t)(n * ROWBYTES)) : "memory");
    for (int r = first; r < first + n; r++) {
        int gs = r; if (gs < 0) gs += LROWS; else if (gs >= LROWS) gs -= LROWS;
        int rr = r % RING; if (rr < 0) rr += RING;
        asm volatile(
            "cp.async.bulk.shared::cta.global.mbarrier::complete_tx::bytes"
            ".L2::cache_hint [%0], [%1], %2, [%3], %4;"
            :: "r"(ring_base + (uint32_t)(rr * ROWBYTES)),
               "l"((const char*)(vb + (size_t)gs * DCOLS)),
               "r"((uint32_t)ROWBYTES), "r"(mbar), "l"(pol_last) : "memory");
    }
}

__device__ __forceinline__ void mbar_wait(uint32_t mbar, uint32_t phase)
{
    uint32_t done;
    asm volatile(
        "{\n\t.reg .pred p;\n\t"
        "mbarrier.try_wait.parity.acquire.cta.shared::cta.b64 p, [%1], %2;\n\t"
        "selp.b32 %0, 1, 0, p;\n\t}"
        : "=r"(done) : "r"(mbar), "r"(phase) : "memory");
    if (!done) {
        asm volatile(
            "{\n\t.reg .pred P1;\n\t"
            "WL_%=:\n\t"
            "mbarrier.try_wait.parity.acquire.cta.shared::cta.b64 P1, [%0], %1, 0x989680;\n\t"
            "@P1 bra.uni WD_%=;\n\t"
            "bra.uni WL_%=;\n\t"
            "WD_%=:\n\t}"
            :: "r"(mbar), "r"(phase) : "memory");
    }
}

__device__ __forceinline__ void sort_win(float* sm, int s, int tx)
{
    int r0 = s % RING; if (r0 < 0) r0 += RING;
    int r1 = r0 + 1; if (r1 >= RING) r1 -= RING;
    int r2 = r1 + 1; if (r2 >= RING) r2 -= RING;
    int r3 = r2 + 1; if (r3 >= RING) r3 -= RING;
    int r4 = r3 + 1; if (r4 >= RING) r4 -= RING;
    float a0 = sm[r0 * DCOLS + tx];
    float a1 = sm[r1 * DCOLS + tx];
    float a2 = sm[r2 * DCOLS + tx];
    float a3 = sm[r3 * DCOLS + tx];
    float a4 = sm[r4 * DCOLS + tx];
    CE(a0, a1); CE(a3, a4); CE(a2, a4);
    CE(a2, a3); CE(a0, a3); CE(a0, a2);
    CE(a1, a4); CE(a1, a3); CE(a1, a2);
    sm[r0 * DCOLS + tx] = a0;
    sm[r1 * DCOLS + tx] = a1;
    sm[r2 * DCOLS + tx] = a2;
    sm[r3 * DCOLS + tx] = a3;
    sm[r4 * DCOLS + tx] = a4;
}

__global__ __launch_bounds__(NTHREADS, 3)
void swd_ring_kernel(const float* __restrict__ v, float* __restrict__ out) {
    extern __shared__ float sm[];
    uint32_t smem_base;
    asm("{ .reg .u64 t; cvta.to.shared.u64 t, %1; cvt.u32.u64 %0, t; }"
        : "=r"(smem_base) : "l"(sm));
    const uint32_t mbb = smem_base + RING * ROWBYTES;

    const int tx = threadIdx.x;
    const int g  = blockIdx.x;
    const int b  = blockIdx.y;

    const int t0 = (g * NTILES) / GPB;
    const int t1 = ((g + 1) * NTILES) / GPB;
    const int n  = t1 - t0;                     // 7 or 8
    const int P0 = t0 * TROWS;

    const float* __restrict__ vb = v   + (size_t)b * LROWS * DCOLS;
    float*       __restrict__ ob = out + (size_t)b * LROWS * DCOLS;

    // Proven policy: input pinned, output streamed.
    uint64_t pol_last, pol_first;
    asm volatile("createpolicy.fractional.L2::evict_last.b64 %0, 1.0;"
                 : "=l"(pol_last));
    asm volatile("createpolicy.fractional.L2::evict_first.b64 %0, 1.0;"
                 : "=l"(pol_first));

    if (tx == 0) {
        #pragma unroll
        for (int j = 0; j < 4; j++)
            asm volatile("mbarrier.init.shared.b64 [%0], 1;"
                         :: "r"(mbb + 8u * j) : "memory");
    }
    __syncthreads();

    // Prime: full 19-row frame for tile 0 only (depth-1 pipeline).
    if (tx == 0) {
        load_rows(vb, P0 - 4, 19, smem_base, mbb + 0, pol_last);
    }

    const int o = (tx + 4) % 5;

    for (int i = 0; i < n; i++) {
        const int P = P0 + i * TROWS;
        mbar_wait(mbb + 8u * (i & 3), (i >> 2) & 1);

        // Early load for tile i+1 (rows P+15..24 ≡ P-21..-12 mod 36):
        // overlaps only store i-2's rows (P-20..-11); wait_group 1 (at most
        // store i-1 outstanding) guarantees store i-2 drained. Disjoint from
        // sort i (P-4..P+14) and store i-1 (P-10..-1).
        if (tx == 0 && i + 1 < n) {
            asm volatile("cp.async.bulk.wait_group 1;" ::: "memory");
            load_rows(vb, P + 15, 10, smem_base,
                      mbb + 8u * ((i + 1) & 3), pol_last);
        }

        // First tile of the chunk also sorts the lower straddling window;
        // steady tiles inherit it (sorted by the previous tile; idempotent).
        if (i == 0) sort_win(sm, P - 4 + o, tx);
        sort_win(sm, P + 1 + o, tx);
        sort_win(sm, P + 6 + o, tx);
        __syncthreads();

        if (tx == 0) {
            asm volatile("fence.proxy.async.shared::cta;" ::: "memory");
            int rr = P % RING;                       // 0..35
            int n1 = RING - rr; if (n1 > TROWS) n1 = TROWS;
            asm volatile(
                "cp.async.bulk.global.shared::cta.bulk_group"
                ".L2::cache_hint [%0], [%1], %2, %3;"
                :: "l"((char*)(ob + (size_t)P * DCOLS)),
                   "r"(smem_base + (uint32_t)(rr * ROWBYTES)),
                   "r"((uint32_t)(n1 * ROWBYTES)), "l"(pol_first)
                : "memory");
            if (n1 < TROWS) {                        // wrapped tail from row 0
                asm volatile(
                    "cp.async.bulk.global.shared::cta.bulk_group"
                    ".L2::cache_hint [%0], [%1], %2, %3;"
                    :: "l"((char*)(ob + (size_t)(P + n1) * DCOLS)),
                       "r"(smem_base),
                       "r"((uint32_t)((TROWS - n1) * ROWBYTES)), "l"(pol_first)
                    : "memory");
            }
            asm volatile("cp.async.bulk.commit_group;" ::: "memory");
        }
    }

    if (tx == 0) {
        asm volatile("cp.async.bulk.wait_group 0;" ::: "memory");
    }
}

extern "C" void kernel_launch(void* const* d_in, const int* in_sizes, int n_in,
                              void* d_out, int out_size) {
    const float* v = (const float*)d_in[2];   // inputs: q (unused), k (unused), v
    float* out     = (float*)d_out;

    cudaFuncSetAttribute(swd_ring_kernel,
                         cudaFuncAttributeMaxDynamicSharedMemorySize, SMEM_BYTES);

    dim3 grid(GPB, 8);                        // 440 CTAs ≈ one wave @ 3/SM
    swd_ring_kernel<<<grid, NTHREADS, SMEM_BYTES>>>(v, out);
}